// round 1
// baseline (speedup 1.0000x reference)
#include <cuda_runtime.h>

// Problem constants (fixed shapes for this problem instance)
#define Bn   2
#define Cc   320
#define Hh   128
#define Ww   256
#define Gg   40
#define CPG  8
#define Dd   48
#define XC   64
#define HW   (Hh*Ww)

// Padded scratch layout for merged = [x, branch1, branch3, branch5]
// channel image padded: rows = H+2 (1 halo top/bottom), row stride = 264,
// pixel (h,w) stored at [(h+1)*264 + (w+5)]  -> vectorized, bounds-check-free fuse conv.
#define MCH    256
#define MROWS  130
#define MSTR   264
#define MCHSZ  (MROWS*MSTR)                 // 34320 floats per channel image
#define MTOTAL ((size_t)Bn*MCH*MCHSZ)       // 17,571,840 floats (~70 MB)

__device__ float g_merged[MTOTAL];

// ---------------------------------------------------------------------------
// packed fp32x2 helpers (exact fp32 math, 2x FFMA throughput on sm_103a)
// ---------------------------------------------------------------------------
__device__ __forceinline__ unsigned long long pk2(float a, float b) {
    unsigned long long r;
    asm("mov.b64 %0, {%1, %2};" : "=l"(r) : "f"(a), "f"(b));
    return r;
}
__device__ __forceinline__ unsigned long long ffma2(unsigned long long a,
                                                    unsigned long long b,
                                                    unsigned long long c) {
    unsigned long long d;
    asm("fma.rn.f32x2 %0, %1, %2, %3;" : "=l"(d) : "l"(a), "l"(b), "l"(c));
    return d;
}
__device__ __forceinline__ float2 upk2(unsigned long long a) {
    float2 f;
    asm("mov.b64 {%0, %1}, %2;" : "=f"(f.x), "=f"(f.y) : "l"(a));
    return f;
}

// ---------------------------------------------------------------------------
// Kernel 1: groupwise-correlation cost volume
// grid (H/4, G, B), block 256 = 64 w-threads x 4 h-rows, 4 px per thread.
// tgt row (8 channels x 4 rows) in zero-left-padded smem; ref in registers.
// Register sliding window over disparity: one LDS.128 per (c, 4 disparities).
// ---------------------------------------------------------------------------
__global__ void __launch_bounds__(256) gwc_kernel(const float* __restrict__ ref,
                                                  const float* __restrict__ tgt,
                                                  float* __restrict__ vol) {
    __shared__ __align__(16) float st[CPG][4][308];   // left pad 51 zeros, idx 51+w
    const int h0  = blockIdx.x * 4;
    const int g   = blockIdx.y;
    const int b   = blockIdx.z;
    const int tid = threadIdx.x;

    // zero smem (covers the padding zones)
    for (int q = tid; q < CPG*4*308; q += 256)
        (&st[0][0][0])[q] = 0.0f;
    __syncthreads();

    const int cbase = b*Cc + g*CPG;
    for (int q = tid; q < CPG*4*Ww; q += 256) {
        int w  = q & 255;
        int hr = (q >> 8) & 3;
        int c  = q >> 10;
        st[c][hr][51 + w] = tgt[(size_t)((cbase + c)*Hh + h0 + hr)*Ww + w];
    }
    __syncthreads();

    const int wt = tid & 63;
    const int hr = tid >> 6;
    const int w0 = wt * 4;

    float4 rr[CPG], prev[CPG];
    #pragma unroll
    for (int c = 0; c < CPG; c++) {
        rr[c]   = *reinterpret_cast<const float4*>(&ref[(size_t)((cbase + c)*Hh + h0 + hr)*Ww + w0]);
        prev[c] = *reinterpret_cast<const float4*>(&st[c][hr][52 + w0]); // tgt[w0+1..w0+4]
    }

    float* vbase = vol + ((size_t)(b*Gg + g)*Dd*Hh + (size_t)(h0 + hr))*Ww + w0;

    #pragma unroll 2
    for (int d0 = 0; d0 < Dd; d0 += 4) {
        float4 A[CPG];
        #pragma unroll
        for (int c = 0; c < CPG; c++)
            A[c] = *reinterpret_cast<const float4*>(&st[c][hr][48 + w0 - d0]); // tgt[w0-d0-3..w0-d0]
        #pragma unroll
        for (int k = 0; k < 4; k++) {
            float a0 = 0.f, a1 = 0.f, a2 = 0.f, a3 = 0.f;
            #pragma unroll
            for (int c = 0; c < CPG; c++) {
                // V[i] = tgt[w0 - d0 - 3 + i], i = 0..6
                float V[7] = { A[c].x, A[c].y, A[c].z, A[c].w,
                               prev[c].x, prev[c].y, prev[c].z };
                a0 += rr[c].x * V[3 - k];
                a1 += rr[c].y * V[4 - k];
                a2 += rr[c].z * V[5 - k];
                a3 += rr[c].w * V[6 - k];
            }
            float4 o = make_float4(a0*0.125f, a1*0.125f, a2*0.125f, a3*0.125f);
            *reinterpret_cast<float4*>(vbase + (size_t)(d0 + k)*HW) = o;
        }
        #pragma unroll
        for (int c = 0; c < CPG; c++) prev[c] = A[c];
    }
}

// ---------------------------------------------------------------------------
// Kernel 2a: zero the padded merged scratch (halo rows/cols must be 0)
// 17,571,840 floats = 4,392,960 float4 = exactly 17160 blocks x 256 threads
// ---------------------------------------------------------------------------
__global__ void __launch_bounds__(256) zero_merged_kernel() {
    size_t i = ((size_t)blockIdx.x * 256 + threadIdx.x) * 4;
    *reinterpret_cast<float4*>(&g_merged[i]) = make_float4(0.f, 0.f, 0.f, 0.f);
}

// ---------------------------------------------------------------------------
// Kernel 2b: fused dynamic conv (dilations 1,3,5) + x copy into merged scratch.
// Reads the big `kernel` tensor exactly once. grid (H, XC, B), block 256 (=W).
// ---------------------------------------------------------------------------
__global__ void __launch_bounds__(256) dynconv_kernel(const float* __restrict__ x,
                                                      const float* __restrict__ ker) {
    const int w = threadIdx.x;
    const int h = blockIdx.x;
    const int c = blockIdx.y;
    const int n = blockIdx.z;

    const float* kp = ker + ((size_t)(n*XC + c)*9*Hh + h)*Ww + w;
    float kv[9];
    #pragma unroll
    for (int t = 0; t < 9; t++) kv[t] = kp[(size_t)t*HW];

    const float* xp = x + (size_t)(n*XC + c)*HW;
    float a1 = 0.f, a3 = 0.f, a5 = 0.f;

    #pragma unroll
    for (int i = 0; i < 3; i++) {
        #pragma unroll
        for (int j = 0; j < 3; j++) {
            const float kvt = kv[i*3 + j];
            {   // dil 1
                int hh = h + (i-1), ww = w + (j-1);
                if ((unsigned)hh < (unsigned)Hh && (unsigned)ww < (unsigned)Ww)
                    a1 += xp[hh*Ww + ww] * kvt;
            }
            {   // dil 3
                int hh = h + (i-1)*3, ww = w + (j-1)*3;
                if ((unsigned)hh < (unsigned)Hh && (unsigned)ww < (unsigned)Ww)
                    a3 += xp[hh*Ww + ww] * kvt;
            }
            {   // dil 5
                int hh = h + (i-1)*5, ww = w + (j-1)*5;
                if ((unsigned)hh < (unsigned)Hh && (unsigned)ww < (unsigned)Ww)
                    a5 += xp[hh*Ww + ww] * kvt;
            }
        }
    }

    const float xc = xp[h*Ww + w];
    const size_t mb = ((size_t)(n*MCH + c)*MROWS + h + 1)*MSTR + w + 5;
    g_merged[mb]                          = xc;   // channels [0,64)   : x
    g_merged[mb + (size_t)1*XC*MCHSZ]     = a1;   // channels [64,128) : dil 1
    g_merged[mb + (size_t)2*XC*MCHSZ]     = a3;   // channels [128,192): dil 3
    g_merged[mb + (size_t)3*XC*MCHSZ]     = a5;   // channels [192,256): dil 5
}

// ---------------------------------------------------------------------------
// Kernel 3: fuse conv 256->64, 3x3, pad 1, ReLU — packed f32x2 direct conv.
// f32x2 lanes = two adjacent OUTPUT channels -> weight pair is a single
// broadcast LDS.64 from smem (no duplication MOV on the hot operand).
// Each thread: 4 w-pixels x 4 output channels. grid (H/4, 16, B), block 256.
// ---------------------------------------------------------------------------
__global__ void __launch_bounds__(256) fuse_kernel(const float* __restrict__ fw,
                                                   float* __restrict__ out) {
    __shared__ __align__(16) float2 sw2[2][256][10];  // [o-pair][in ch][tap(9)+pad]

    const int h0  = blockIdx.x * 4;
    const int og  = blockIdx.y;        // 16 groups of 4 output channels
    const int n   = blockIdx.z;
    const int o0  = og * 4;
    const int tid = threadIdx.x;

    // stage weights for this block's 4 output channels, paired (o, o+1)
    for (int q = tid; q < 2*256*9; q += 256) {
        int op = q / (256*9);
        int r  = q % (256*9);
        int i  = r / 9, t = r % 9;
        int o  = o0 + op*2;
        sw2[op][i][t] = make_float2(fw[((size_t)o*256 + i)*9 + t],
                                    fw[((size_t)(o+1)*256 + i)*9 + t]);
    }
    __syncthreads();

    const int wt = tid & 63, hr = tid >> 6;
    const int w0 = wt * 4;
    const int h  = h0 + hr;

    // padded rows h..h+2 correspond to unpadded hh = h-1..h+1; col base m = w0+4 (= w0-1)
    const float* mbase = g_merged + (size_t)n*MCH*MCHSZ + (size_t)h*MSTR + (w0 + 4);

    unsigned long long acc[4][2];
    #pragma unroll
    for (int px = 0; px < 4; px++) { acc[px][0] = 0ull; acc[px][1] = 0ull; }

#define LOAD_CH(IDX, R4, R2) do {                                              \
        const float* _m = mbase + (size_t)(IDX)*MCHSZ;                          \
        _Pragma("unroll")                                                       \
        for (int _r = 0; _r < 3; _r++) {                                        \
            R4[_r] = *reinterpret_cast<const float4*>(_m + _r*MSTR);            \
            R2[_r] = *reinterpret_cast<const float2*>(_m + _r*MSTR + 4);        \
        }                                                                       \
    } while (0)

#define FUSE_STEP(CH, R4, R2) do {                                              \
        unsigned long long vv[3][6];                                            \
        _Pragma("unroll")                                                       \
        for (int _r = 0; _r < 3; _r++) {                                        \
            vv[_r][0] = pk2(R4[_r].x, R4[_r].x);                                \
            vv[_r][1] = pk2(R4[_r].y, R4[_r].y);                                \
            vv[_r][2] = pk2(R4[_r].z, R4[_r].z);                                \
            vv[_r][3] = pk2(R4[_r].w, R4[_r].w);                                \
            vv[_r][4] = pk2(R2[_r].x, R2[_r].x);                                \
            vv[_r][5] = pk2(R2[_r].y, R2[_r].y);                                \
        }                                                                       \
        _Pragma("unroll")                                                       \
        for (int _op = 0; _op < 2; _op++) {                                     \
            const float2* _wr = &sw2[_op][CH][0];                               \
            _Pragma("unroll")                                                   \
            for (int _kh = 0; _kh < 3; _kh++) {                                 \
                _Pragma("unroll")                                               \
                for (int _kw = 0; _kw < 3; _kw++) {                             \
                    float2 _wv = _wr[_kh*3 + _kw];                              \
                    unsigned long long _wp = pk2(_wv.x, _wv.y);                 \
                    _Pragma("unroll")                                           \
                    for (int _px = 0; _px < 4; _px++)                           \
                        acc[_px][_op] = ffma2(vv[_kh][_kw + _px], _wp,          \
                                              acc[_px][_op]);                   \
                }                                                               \
            }                                                                   \
        }                                                                       \
    } while (0)

    float4 a4[3]; float2 a2[3];
    LOAD_CH(0, a4, a2);

    #pragma unroll 1
    for (int i = 0; i < 256; i += 2) {
        float4 b4[3]; float2 b2[3];
        LOAD_CH(i + 1, b4, b2);              // prefetch odd channel
        FUSE_STEP(i, a4, a2);
        const int inext = (i + 2 < 256) ? (i + 2) : 255;  // clamp (harmless reread)
        LOAD_CH(inext, a4, a2);              // prefetch next even channel
        FUSE_STEP(i + 1, b4, b2);
    }

    float* ob = out + ((size_t)(n*XC)*Hh + h)*Ww + w0;
    #pragma unroll
    for (int op = 0; op < 2; op++) {
        const int o = o0 + op*2;
        #pragma unroll
        for (int px = 0; px < 4; px++) {
            float2 f = upk2(acc[px][op]);
            ob[(size_t)o*HW + px]       = fmaxf(f.x, 0.f);
            ob[(size_t)(o+1)*HW + px]   = fmaxf(f.y, 0.f);
        }
    }
#undef LOAD_CH
#undef FUSE_STEP
}

// ---------------------------------------------------------------------------
extern "C" void kernel_launch(void* const* d_in, const int* in_sizes, int n_in,
                              void* d_out, int out_size) {
    const float* ref = (const float*)d_in[0];
    const float* tgt = (const float*)d_in[1];
    const float* x   = (const float*)d_in[2];
    const float* ker = (const float*)d_in[3];
    const float* fw  = (const float*)d_in[4];
    // d_in[5] = maxdisp (48), d_in[6] = num_groups (40) — compile-time constants here.

    float* vol  = (float*)d_out;                              // [2,40,48,128,256]
    float* out2 = vol + (size_t)Bn*Gg*Dd*HW;                  // [2,64,128,256]

    // independent: cost volume
    gwc_kernel<<<dim3(Hh/4, Gg, Bn), 256>>>(ref, tgt, vol);

    // zero padded scratch, then dynamic conv fills interior, then fuse conv
    zero_merged_kernel<<<(unsigned)(MTOTAL/4/256), 256>>>();
    dynconv_kernel<<<dim3(Hh, XC, Bn), 256>>>(x, ker);
    fuse_kernel<<<dim3(Hh/4, XC/4, Bn), 256>>>(fw, out2);
}

// round 3
// speedup vs baseline: 1.7428x; 1.7428x over previous
#include <cuda_runtime.h>
#include <cstdint>

// Problem constants
#define Bn   2
#define Cc   320
#define Hh   128
#define Ww   256
#define Gg   40
#define CPG  8
#define Dd   48
#define XC   64
#define HW   (Hh*Ww)

// Padded scratch layout for merged = [x, branch1, branch3, branch5]
#define MCH    256
#define MROWS  130
#define MSTR   264
#define MCHSZ  (MROWS*MSTR)
#define MTOTAL ((size_t)Bn*MCH*MCHSZ)

__device__ float g_merged[MTOTAL];
__device__ float g_fwr[32*72*64];     // tf32-rounded weights, [chunk][k(72)][o(64)]

// ---------------------------------------------------------------------------
// helpers
// ---------------------------------------------------------------------------
__device__ __forceinline__ float tf32r(float f) {      // round-to-nearest tf32
    uint32_t u; asm("cvt.rna.tf32.f32 %0, %1;" : "=r"(u) : "f"(f));
    return __uint_as_float(u);
}
__device__ __forceinline__ uint32_t smem_u32(const void* p) {
    uint32_t a;
    asm("{ .reg .u64 t; cvta.to.shared.u64 t, %1; cvt.u32.u64 %0, t; }" : "=r"(a) : "l"(p));
    return a;
}
__device__ __forceinline__ void cpasync16(uint32_t dst, const void* src) {
    asm volatile("cp.async.cg.shared.global [%0], [%1], 16;" :: "r"(dst), "l"(src) : "memory");
}
#define CP_COMMIT() asm volatile("cp.async.commit_group;" ::: "memory")
#define CP_WAIT(N)  asm volatile("cp.async.wait_group %0;" :: "n"(N) : "memory")

__device__ __forceinline__ void mma_tf32(float* c, const uint32_t* a,
                                         uint32_t b0, uint32_t b1) {
    asm volatile("mma.sync.aligned.m16n8k8.row.col.f32.tf32.tf32.f32 "
        "{%0,%1,%2,%3}, {%4,%5,%6,%7}, {%8,%9}, {%0,%1,%2,%3};"
        : "+f"(c[0]), "+f"(c[1]), "+f"(c[2]), "+f"(c[3])
        : "r"(a[0]), "r"(a[1]), "r"(a[2]), "r"(a[3]), "r"(b0), "r"(b1));
}

// ---------------------------------------------------------------------------
// Kernel 1: groupwise-correlation cost volume (exact fp32)
// ---------------------------------------------------------------------------
__global__ void __launch_bounds__(256) gwc_kernel(const float* __restrict__ ref,
                                                  const float* __restrict__ tgt,
                                                  float* __restrict__ vol) {
    __shared__ __align__(16) float st[CPG][4][308];
    const int h0  = blockIdx.x * 4;
    const int g   = blockIdx.y;
    const int b   = blockIdx.z;
    const int tid = threadIdx.x;

    for (int q = tid; q < CPG*4*308; q += 256)
        (&st[0][0][0])[q] = 0.0f;
    __syncthreads();

    const int cbase = b*Cc + g*CPG;
    for (int q = tid; q < CPG*4*Ww; q += 256) {
        int w  = q & 255;
        int hr = (q >> 8) & 3;
        int c  = q >> 10;
        st[c][hr][51 + w] = tgt[(size_t)((cbase + c)*Hh + h0 + hr)*Ww + w];
    }
    __syncthreads();

    const int wt = tid & 63;
    const int hr = tid >> 6;
    const int w0 = wt * 4;

    float4 rr[CPG], prev[CPG];
    #pragma unroll
    for (int c = 0; c < CPG; c++) {
        rr[c]   = *reinterpret_cast<const float4*>(&ref[(size_t)((cbase + c)*Hh + h0 + hr)*Ww + w0]);
        prev[c] = *reinterpret_cast<const float4*>(&st[c][hr][52 + w0]);
    }

    float* vbase = vol + ((size_t)(b*Gg + g)*Dd*Hh + (size_t)(h0 + hr))*Ww + w0;

    #pragma unroll 2
    for (int d0 = 0; d0 < Dd; d0 += 4) {
        float4 A[CPG];
        #pragma unroll
        for (int c = 0; c < CPG; c++)
            A[c] = *reinterpret_cast<const float4*>(&st[c][hr][48 + w0 - d0]);
        #pragma unroll
        for (int k = 0; k < 4; k++) {
            float a0 = 0.f, a1 = 0.f, a2 = 0.f, a3 = 0.f;
            #pragma unroll
            for (int c = 0; c < CPG; c++) {
                float V[7] = { A[c].x, A[c].y, A[c].z, A[c].w,
                               prev[c].x, prev[c].y, prev[c].z };
                a0 += rr[c].x * V[3 - k];
                a1 += rr[c].y * V[4 - k];
                a2 += rr[c].z * V[5 - k];
                a3 += rr[c].w * V[6 - k];
            }
            float4 o = make_float4(a0*0.125f, a1*0.125f, a2*0.125f, a3*0.125f);
            *reinterpret_cast<float4*>(vbase + (size_t)(d0 + k)*HW) = o;
        }
        #pragma unroll
        for (int c = 0; c < CPG; c++) prev[c] = A[c];
    }
}

// ---------------------------------------------------------------------------
// Kernel 2a: zero only the halo of the padded merged scratch (interior is
// fully written by dynconv). grid = 512 channel-images, 256 threads.
// ---------------------------------------------------------------------------
__global__ void __launch_bounds__(256) halo_zero_kernel() {
    const int img = blockIdx.x;
    const int tid = threadIdx.x;
    float* base = g_merged + (size_t)img*MCHSZ;
    for (int q = tid; q < MSTR; q += 256) {
        base[q] = 0.f;                        // padded row 0
        base[(size_t)129*MSTR + q] = 0.f;     // padded row 129
    }
    for (int i = tid; i < 1024; i += 256) {   // side pads, rows 1..128
        int row = 1 + (i >> 3);
        int c8  = i & 7;
        int col = (c8 < 5) ? c8 : (256 + c8); // 0..4 and 261..263
        base[(size_t)row*MSTR + col] = 0.f;
    }
}

// ---------------------------------------------------------------------------
// Kernel 2b: fused dynamic conv; outputs written tf32-rounded.
// ---------------------------------------------------------------------------
__global__ void __launch_bounds__(256) dynconv_kernel(const float* __restrict__ x,
                                                      const float* __restrict__ ker) {
    const int w = threadIdx.x;
    const int h = blockIdx.x;
    const int c = blockIdx.y;
    const int n = blockIdx.z;

    const float* kp = ker + ((size_t)(n*XC + c)*9*Hh + h)*Ww + w;
    float kv[9];
    #pragma unroll
    for (int t = 0; t < 9; t++) kv[t] = kp[(size_t)t*HW];

    const float* xp = x + (size_t)(n*XC + c)*HW;
    float a1 = 0.f, a3 = 0.f, a5 = 0.f;

    #pragma unroll
    for (int i = 0; i < 3; i++) {
        #pragma unroll
        for (int j = 0; j < 3; j++) {
            const float kvt = kv[i*3 + j];
            {   int hh = h + (i-1), ww = w + (j-1);
                if ((unsigned)hh < (unsigned)Hh && (unsigned)ww < (unsigned)Ww)
                    a1 += xp[hh*Ww + ww] * kvt; }
            {   int hh = h + (i-1)*3, ww = w + (j-1)*3;
                if ((unsigned)hh < (unsigned)Hh && (unsigned)ww < (unsigned)Ww)
                    a3 += xp[hh*Ww + ww] * kvt; }
            {   int hh = h + (i-1)*5, ww = w + (j-1)*5;
                if ((unsigned)hh < (unsigned)Hh && (unsigned)ww < (unsigned)Ww)
                    a5 += xp[hh*Ww + ww] * kvt; }
        }
    }

    const float xc = xp[h*Ww + w];
    const size_t mb = ((size_t)(n*MCH + c)*MROWS + h + 1)*MSTR + w + 5;
    g_merged[mb]                      = tf32r(xc);
    g_merged[mb + (size_t)1*XC*MCHSZ] = tf32r(a1);
    g_merged[mb + (size_t)2*XC*MCHSZ] = tf32r(a3);
    g_merged[mb + (size_t)3*XC*MCHSZ] = tf32r(a5);
}

// ---------------------------------------------------------------------------
// Kernel 2c: pre-round fuse weights to tf32 and transpose to [chunk][k][o]
// ---------------------------------------------------------------------------
__global__ void __launch_bounds__(256) prep_fw_kernel(const float* __restrict__ fw) {
    int gidx = blockIdx.x * 256 + threadIdx.x;       // 576 * 256 = 147456
    int o = gidx & 63;
    int kglob = gidx >> 6;
    g_fwr[gidx] = tf32r(fw[(size_t)o*2304 + kglob]); // dest idx = kglob*64 + o
}

// ---------------------------------------------------------------------------
// Kernel 3: fuse conv as implicit GEMM via mma.sync.m16n8k8.tf32.
// CTA = 128 w x 2 h rows (M=256 px) x N=64 outs; 8 warps x (M=32, N=64).
// K loop: 32 chunks of 72 (8 in-ch x 9 taps); cp.async double-buffered
// A patch [8ch x 4rows x 132] and B [72 x 64] (XOR-swizzled).
// ---------------------------------------------------------------------------
#define SMF_B0  0
#define SMF_B1  18432
#define SMF_P0  36864
#define SMF_P1  53760
#define SMF_TOT 70656

__global__ void __launch_bounds__(256, 2) fuse_mma_kernel(float* __restrict__ out) {
    extern __shared__ __align__(16) char smem[];
    const uint32_t sb = smem_u32(smem);
    const int tid  = threadIdx.x;
    const int wid  = tid >> 5;
    const int lane = tid & 31;
    const int q    = lane & 3;
    const int e    = lane >> 2;
    const int w0   = blockIdx.x * 128;
    const int h    = blockIdx.y * 2;       // rows h, h+1
    const int n    = blockIdx.z;
    const int colb = w0 + 4;

    // ---- per-thread constant A K-offsets (float indices into Psh) ----
    int offs0[9], offs1[9];
    #pragma unroll
    for (int s = 0; s < 9; s++) {
        int k0 = s*8 + q, k1 = k0 + 4;
        offs0[s] = ((k0/9)*4 + (k0%9)/3)*132 + (k0 % 3);
        offs1[s] = ((k1/9)*4 + (k1%9)/3)*132 + (k1 % 3);
    }
    // A pixel bases per m16 tile
    int baseT[2];
    #pragma unroll
    for (int t = 0; t < 2; t++) {
        int p = wid*32 + t*16 + e;
        baseT[t] = (p >> 7)*132 + (p & 127);
    }

    // ---- staging lambda (cp.async) ----
    auto stage = [&](int blk, int j) {
        // patch: 1056 x 16B
        const uint32_t pdst = sb + (j ? SMF_P1 : SMF_P0);
        for (int u = tid; u < 1056; u += 256) {
            int c = u / 132, rm = u % 132;
            int r = rm / 33, f = rm % 33;
            const float* src = g_merged
                + ((size_t)((n*MCH + blk*8 + c)*MROWS + h + r))*MSTR + colb + f*4;
            cpasync16(pdst + (uint32_t)(((c*4 + r)*132 + f*4)*4), src);
        }
        // B: 1152 x 16B, XOR swizzle on 8-float column groups
        const uint32_t bdst = sb + (j ? SMF_B1 : SMF_B0);
        const float* fsrc = g_fwr + (size_t)blk*72*64;
        for (int u = tid; u < 1152; u += 256) {
            int k = u >> 4, g16 = u & 15;
            int n8 = g16 >> 1, half = g16 & 1;
            int dcol = ((n8 ^ (k & 3)) << 3) + half*4;
            cpasync16(bdst + (uint32_t)((k*64 + dcol)*4), fsrc + k*64 + g16*4);
        }
    };

    float acc[2][8][4];
    #pragma unroll
    for (int t = 0; t < 2; t++)
        #pragma unroll
        for (int nt = 0; nt < 8; nt++)
            #pragma unroll
            for (int r = 0; r < 4; r++) acc[t][nt][r] = 0.f;

    stage(0, 0);
    CP_COMMIT();

    for (int blk = 0; blk < 32; blk++) {
        const int j = blk & 1;
        if (blk < 31) { stage(blk + 1, j ^ 1); CP_COMMIT(); }
        if (blk < 31) CP_WAIT(1); else CP_WAIT(0);
        __syncthreads();

        const uint32_t* Pbuf = (const uint32_t*)(smem + (j ? SMF_P1 : SMF_P0));
        const uint32_t* Bbuf = (const uint32_t*)(smem + (j ? SMF_B1 : SMF_B0));

        #pragma unroll
        for (int s = 0; s < 9; s++) {
            uint32_t a[2][4];
            #pragma unroll
            for (int t = 0; t < 2; t++) {
                const uint32_t* A0 = Pbuf + baseT[t] + offs0[s];
                const uint32_t* A1 = Pbuf + baseT[t] + offs1[s];
                a[t][0] = A0[0]; a[t][1] = A0[8];
                a[t][2] = A1[0]; a[t][3] = A1[8];
            }
            const uint32_t* Bp = Bbuf + (s*8 + q)*64 + e;
            #pragma unroll
            for (int nt = 0; nt < 8; nt++) {
                uint32_t b0 = Bp[((nt ^ q) << 3)];
                uint32_t b1 = Bp[256 + ((nt ^ q) << 3)];
                mma_tf32(acc[0][nt], a[0], b0, b1);
                mma_tf32(acc[1][nt], a[1], b0, b1);
            }
        }
        __syncthreads();
    }

    // ---- epilogue: ReLU + store ----
    float* ob = out + (size_t)n*XC*HW;
    #pragma unroll
    for (int t = 0; t < 2; t++) {
        int p0 = wid*32 + t*16 + e;
        int p1 = p0 + 8;
        int i0 = (h + (p0 >> 7))*Ww + w0 + (p0 & 127);
        int i1 = (h + (p1 >> 7))*Ww + w0 + (p1 & 127);
        #pragma unroll
        for (int nt = 0; nt < 8; nt++) {
            int o = nt*8 + q*2;
            ob[(size_t)o*HW + i0]       = fmaxf(acc[t][nt][0], 0.f);
            ob[(size_t)(o+1)*HW + i0]   = fmaxf(acc[t][nt][1], 0.f);
            ob[(size_t)o*HW + i1]       = fmaxf(acc[t][nt][2], 0.f);
            ob[(size_t)(o+1)*HW + i1]   = fmaxf(acc[t][nt][3], 0.f);
        }
    }
}

// ---------------------------------------------------------------------------
extern "C" void kernel_launch(void* const* d_in, const int* in_sizes, int n_in,
                              void* d_out, int out_size) {
    const float* ref = (const float*)d_in[0];
    const float* tgt = (const float*)d_in[1];
    const float* x   = (const float*)d_in[2];
    const float* ker = (const float*)d_in[3];
    const float* fw  = (const float*)d_in[4];

    float* vol  = (float*)d_out;
    float* out2 = vol + (size_t)Bn*Gg*Dd*HW;

    gwc_kernel<<<dim3(Hh/4, Gg, Bn), 256>>>(ref, tgt, vol);

    halo_zero_kernel<<<Bn*MCH, 256>>>();
    prep_fw_kernel<<<576, 256>>>(fw);
    dynconv_kernel<<<dim3(Hh, XC, Bn), 256>>>(x, ker);

    cudaFuncSetAttribute(fuse_mma_kernel,
                         cudaFuncAttributeMaxDynamicSharedMemorySize, SMF_TOT);
    fuse_mma_kernel<<<dim3(2, Hh/2, Bn), 256, SMF_TOT>>>(out2);
}